// round 14
// baseline (speedup 1.0000x reference)
#include <cuda_runtime.h>
#include <cuda_fp16.h>
#include <cstdint>
#include <cstddef>

#define DIMD   1024
#define TT     8192     // B*N = B*M rows
#define HD     64       // head dim
#define SEQ    2048

// ---------------- scratch ----------------
__device__ float  g_Qp [TT * DIMD];   // fp32 Q projection (residual)
__device__ float  g_Oh [TT * DIMD];   // fp32 attention out (residual for final gemm)
__device__ __half g_Qh [TT * DIMD];
__device__ __half g_Kh [TT * DIMD];
__device__ __half g_Vh [TT * DIMD];
__device__ __half g_OhH[TT * DIMD];

// =========================== helpers =================================
__device__ __forceinline__ uint32_t smem_u32(const void* p) {
    uint32_t a;
    asm("{ .reg .u64 t; cvta.to.shared.u64 t, %1; cvt.u32.u64 %0, t; }"
        : "=r"(a) : "l"(p));
    return a;
}

#define LDSM_X4(R0, R1, R2, R3, addr) \
    asm volatile("ldmatrix.sync.aligned.m8n8.x4.shared.b16 {%0,%1,%2,%3}, [%4];" \
                 : "=r"(R0), "=r"(R1), "=r"(R2), "=r"(R3) : "r"(addr))

#define LDSM_X4_T(R0, R1, R2, R3, addr) \
    asm volatile("ldmatrix.sync.aligned.m8n8.x4.trans.shared.b16 {%0,%1,%2,%3}, [%4];" \
                 : "=r"(R0), "=r"(R1), "=r"(R2), "=r"(R3) : "r"(addr))

#define MMA_F16(c, a, b0, b1) \
    asm volatile("mma.sync.aligned.m16n8k16.row.col.f32.f16.f16.f32 " \
                 "{%0,%1,%2,%3}, {%4,%5,%6,%7}, {%8,%9}, {%0,%1,%2,%3};" \
                 : "+f"((c)[0]), "+f"((c)[1]), "+f"((c)[2]), "+f"((c)[3]) \
                 : "r"((a)[0]), "r"((a)[1]), "r"((a)[2]), "r"((a)[3]), \
                   "r"(b0), "r"(b1))

__device__ __forceinline__ uint32_t pkhf(float lo, float hi) {
    uint32_t d;
    asm("cvt.rn.f16x2.f32 %0, %1, %2;" : "=r"(d) : "f"(hi), "f"(lo));
    return d;
}
__device__ __forceinline__ void cvt8h(const float* f, uint32_t* o) {
    #pragma unroll
    for (int i = 0; i < 4; i++) o[i] = pkhf(f[2 * i], f[2 * i + 1]);
}

// swizzled smem address: 128B rows, 8 chunks of 16B, chunk c XOR (r&7)
__device__ __forceinline__ uint32_t sw_addr(uint32_t base, int r, int c) {
    return base + (uint32_t)(r * 128) + (uint32_t)(((c ^ (r & 7)) & 7) << 4);
}

__device__ __forceinline__ void st16(uint32_t a, uint4 v) {
    asm volatile("st.shared.v4.b32 [%0], {%1,%2,%3,%4};"
                 :: "r"(a), "r"(v.x), "r"(v.y), "r"(v.z), "r"(v.w));
}

// ================================================================================
// Fused projection GEMM (Q/K/V in ONE launch, blockIdx.z selects projection):
//   z=0: Qp/Qh = Xq @ Wq^T + bq   (also writes fp32 Qp)
//   z=1: Kh    = Xk @ Wk^T + bk
//   z=2: Vh    = Xk @ Wv^T + bv
// 128x128 tile, BK=32, 256 threads (8 warps, 2m x 4n), warp tile 64x32.
// ================================================================================
#define GEMM_SMEM (2 * 32768)

__global__ void __launch_bounds__(256)
gemm_proj3(const float* __restrict__ Xq, const float* __restrict__ Xk,
           const float* __restrict__ Wq, const float* __restrict__ Wk,
           const float* __restrict__ Wv,
           const float* __restrict__ bq, const float* __restrict__ bk,
           const float* __restrict__ bv,
           float* __restrict__ Qp,
           __half* __restrict__ Qh, __half* __restrict__ Kh,
           __half* __restrict__ Vh)
{
    extern __shared__ char sm[];
    const uint32_t sb = smem_u32(sm);

    const int z = blockIdx.z;
    const float* X    = (z == 0) ? Xq : Xk;
    const float* W    = (z == 0) ? Wq : (z == 1) ? Wk : Wv;
    const float* bias = (z == 0) ? bq : (z == 1) ? bk : bv;
    __half* CH        = (z == 0) ? Qh : (z == 1) ? Kh : Vh;

    const int t    = threadIdx.x;
    const int w    = t >> 5;
    const int lane = t & 31;
    const int wm   = w >> 2;
    const int wn   = w & 3;
    const int bn   = blockIdx.x;
    const int bm   = blockIdx.y;

    float acc[4][4][4];
    #pragma unroll
    for (int mi = 0; mi < 4; mi++)
        #pragma unroll
        for (int ni = 0; ni < 4; ni++)
            #pragma unroll
            for (int q = 0; q < 4; q++) acc[mi][ni][q] = 0.0f;

    float stA[2][8], stB[2][8];
    #pragma unroll
    for (int s = 0; s < 2; s++) {
        int idx = t + 256 * s;
        int r = idx >> 2, seg = idx & 3;
        const float* pA = X + (size_t)(bm * 128 + r) * DIMD + seg * 8;
        const float* pB = W + (size_t)(bn * 128 + r) * DIMD + seg * 8;
        *(float4*)&stA[s][0] = *(const float4*)(pA);
        *(float4*)&stA[s][4] = *(const float4*)(pA + 4);
        *(float4*)&stB[s][0] = *(const float4*)(pB);
        *(float4*)&stB[s][4] = *(const float4*)(pB + 4);
    }

    const int rin = lane & 15;
    const int hb  = lane >> 4;

    for (int ch = 0; ch < 32; ch++) {
        const uint32_t Ab = sb + (uint32_t)(ch & 1) * 32768u;
        const uint32_t Bb = Ab + 16384u;

        #pragma unroll
        for (int s = 0; s < 2; s++) {
            int idx = t + 256 * s;
            int r = idx >> 2, seg = idx & 3;
            uint32_t h[4];
            cvt8h(stA[s], h);
            st16(sw_addr(Ab, r, seg), make_uint4(h[0], h[1], h[2], h[3]));
            cvt8h(stB[s], h);
            st16(sw_addr(Bb, r, seg), make_uint4(h[0], h[1], h[2], h[3]));
        }
        __syncthreads();

        if (ch + 1 < 32) {
            const int k0 = (ch + 1) * 32;
            #pragma unroll
            for (int s = 0; s < 2; s++) {
                int idx = t + 256 * s;
                int r = idx >> 2, seg = idx & 3;
                const float* pA = X + (size_t)(bm * 128 + r) * DIMD + k0 + seg * 8;
                const float* pB = W + (size_t)(bn * 128 + r) * DIMD + k0 + seg * 8;
                *(float4*)&stA[s][0] = *(const float4*)(pA);
                *(float4*)&stA[s][4] = *(const float4*)(pA + 4);
                *(float4*)&stB[s][0] = *(const float4*)(pB);
                *(float4*)&stB[s][4] = *(const float4*)(pB + 4);
            }
        }

        #pragma unroll
        for (int ks = 0; ks < 2; ks++) {
            const int chi = ks * 2 + hb;
            uint32_t afr[4][4];
            #pragma unroll
            for (int mi = 0; mi < 4; mi++)
                LDSM_X4(afr[mi][0], afr[mi][1], afr[mi][2], afr[mi][3],
                        sw_addr(Ab, wm * 64 + mi * 16 + rin, chi));
            uint32_t bh[2][4];
            #pragma unroll
            for (int pi = 0; pi < 2; pi++)
                LDSM_X4(bh[pi][0], bh[pi][1], bh[pi][2], bh[pi][3],
                        sw_addr(Bb, wn * 32 + pi * 16 + rin, chi));
            #pragma unroll
            for (int mi = 0; mi < 4; mi++)
                #pragma unroll
                for (int ni = 0; ni < 4; ni++)
                    MMA_F16(acc[mi][ni], afr[mi],
                            bh[ni >> 1][ni & 1], bh[ni >> 1][(ni & 1) + 2]);
        }
        __syncthreads();
    }

    const int rbase = bm * 128 + wm * 64;
    const int cbase = bn * 128 + wn * 32;
    float bb[4][2];
    #pragma unroll
    for (int ni = 0; ni < 4; ni++) {
        int c0 = cbase + ni * 8 + (lane & 3) * 2;
        bb[ni][0] = bias[c0];
        bb[ni][1] = bias[c0 + 1];
    }

    #pragma unroll
    for (int mi = 0; mi < 4; mi++) {
        #pragma unroll
        for (int ni = 0; ni < 4; ni++) {
            int r0 = rbase + mi * 16 + (lane >> 2);
            int c0 = cbase + ni * 8 + (lane & 3) * 2;
            float o0 = acc[mi][ni][0] + bb[ni][0];
            float o1 = acc[mi][ni][1] + bb[ni][1];
            float o2 = acc[mi][ni][2] + bb[ni][0];
            float o3 = acc[mi][ni][3] + bb[ni][1];
            *(uint32_t*)&CH[(size_t)r0 * DIMD + c0]       = pkhf(o0, o1);
            *(uint32_t*)&CH[(size_t)(r0 + 8) * DIMD + c0] = pkhf(o2, o3);
            if (z == 0) {
                *(float2*)&Qp[(size_t)r0 * DIMD + c0]       = make_float2(o0, o1);
                *(float2*)&Qp[(size_t)(r0 + 8) * DIMD + c0] = make_float2(o2, o3);
            }
        }
    }
}

// ================================================================================
// Output GEMM (R9-proven): out = R + relu(Xh @ W^T + bias), Xh fp16, R/out fp32.
// ================================================================================
__global__ void __launch_bounds__(256)
gemm_out(const __half* __restrict__ X, const float* __restrict__ W,
         const float* __restrict__ bias, const float* __restrict__ R,
         float* __restrict__ C)
{
    extern __shared__ char sm[];
    const uint32_t sb = smem_u32(sm);

    const int t    = threadIdx.x;
    const int w    = t >> 5;
    const int lane = t & 31;
    const int wm   = w >> 2;
    const int wn   = w & 3;
    const int bn   = blockIdx.x;
    const int bm   = blockIdx.y;

    float acc[4][4][4];
    #pragma unroll
    for (int mi = 0; mi < 4; mi++)
        #pragma unroll
        for (int ni = 0; ni < 4; ni++)
            #pragma unroll
            for (int q = 0; q < 4; q++) acc[mi][ni][q] = 0.0f;

    uint4 stA[2];
    float stB[2][8];
    #pragma unroll
    for (int s = 0; s < 2; s++) {
        int idx = t + 256 * s;
        int r = idx >> 2, seg = idx & 3;
        stA[s] = *(const uint4*)&X[(size_t)(bm * 128 + r) * DIMD + seg * 8];
        const float* pB = W + (size_t)(bn * 128 + r) * DIMD + seg * 8;
        *(float4*)&stB[s][0] = *(const float4*)(pB);
        *(float4*)&stB[s][4] = *(const float4*)(pB + 4);
    }

    const int rin = lane & 15;
    const int hb  = lane >> 4;

    for (int ch = 0; ch < 32; ch++) {
        const uint32_t Ab = sb + (uint32_t)(ch & 1) * 32768u;
        const uint32_t Bb = Ab + 16384u;

        #pragma unroll
        for (int s = 0; s < 2; s++) {
            int idx = t + 256 * s;
            int r = idx >> 2, seg = idx & 3;
            st16(sw_addr(Ab, r, seg), stA[s]);
            uint32_t h[4];
            cvt8h(stB[s], h);
            st16(sw_addr(Bb, r, seg), make_uint4(h[0], h[1], h[2], h[3]));
        }
        __syncthreads();

        if (ch + 1 < 32) {
            const int k0 = (ch + 1) * 32;
            #pragma unroll
            for (int s = 0; s < 2; s++) {
                int idx = t + 256 * s;
                int r = idx >> 2, seg = idx & 3;
                stA[s] = *(const uint4*)&X[(size_t)(bm * 128 + r) * DIMD + k0 + seg * 8];
                const float* pB = W + (size_t)(bn * 128 + r) * DIMD + k0 + seg * 8;
                *(float4*)&stB[s][0] = *(const float4*)(pB);
                *(float4*)&stB[s][4] = *(const float4*)(pB + 4);
            }
        }

        #pragma unroll
        for (int ks = 0; ks < 2; ks++) {
            const int chi = ks * 2 + hb;
            uint32_t afr[4][4];
            #pragma unroll
            for (int mi = 0; mi < 4; mi++)
                LDSM_X4(afr[mi][0], afr[mi][1], afr[mi][2], afr[mi][3],
                        sw_addr(Ab, wm * 64 + mi * 16 + rin, chi));
            uint32_t bh[2][4];
            #pragma unroll
            for (int pi = 0; pi < 2; pi++)
                LDSM_X4(bh[pi][0], bh[pi][1], bh[pi][2], bh[pi][3],
                        sw_addr(Bb, wn * 32 + pi * 16 + rin, chi));
            #pragma unroll
            for (int mi = 0; mi < 4; mi++)
                #pragma unroll
                for (int ni = 0; ni < 4; ni++)
                    MMA_F16(acc[mi][ni], afr[mi],
                            bh[ni >> 1][ni & 1], bh[ni >> 1][(ni & 1) + 2]);
        }
        __syncthreads();
    }

    const int rbase = bm * 128 + wm * 64;
    const int cbase = bn * 128 + wn * 32;
    float bb[4][2];
    #pragma unroll
    for (int ni = 0; ni < 4; ni++) {
        int c0 = cbase + ni * 8 + (lane & 3) * 2;
        bb[ni][0] = bias[c0];
        bb[ni][1] = bias[c0 + 1];
    }

    #pragma unroll
    for (int mi = 0; mi < 4; mi++) {
        #pragma unroll
        for (int ni = 0; ni < 4; ni++) {
            int r0 = rbase + mi * 16 + (lane >> 2);
            int c0 = cbase + ni * 8 + (lane & 3) * 2;
            float2 ra = *(const float2*)&R[(size_t)r0 * DIMD + c0];
            float2 rb = *(const float2*)&R[(size_t)(r0 + 8) * DIMD + c0];
            float o0 = fmaxf(acc[mi][ni][0] + bb[ni][0], 0.0f) + ra.x;
            float o1 = fmaxf(acc[mi][ni][1] + bb[ni][1], 0.0f) + ra.y;
            float o2 = fmaxf(acc[mi][ni][2] + bb[ni][0], 0.0f) + rb.x;
            float o3 = fmaxf(acc[mi][ni][3] + bb[ni][1], 0.0f) + rb.y;
            *(float2*)&C[(size_t)r0 * DIMD + c0]       = make_float2(o0, o1);
            *(float2*)&C[(size_t)(r0 + 8) * DIMD + c0] = make_float2(o2, o3);
        }
    }
}

// ================================================================================
// Tensor-core flash attention (R13-proven): Br=128, Bc=64, d=64, 4 warps,
// 32 Q-rows/warp, keys in 32-wide halves. fp16 in, fp32 accum, no max-sub.
// ================================================================================
#define ATT_SMEM (16384 + 8192 + 8192)

__global__ void __launch_bounds__(128, 2)
attn_mma(const __half* __restrict__ Qh, const __half* __restrict__ Kh,
         const __half* __restrict__ Vh, const float* __restrict__ Qp,
         float* __restrict__ Oh, __half* __restrict__ OhH)
{
    extern __shared__ char smatt[];
    const uint32_t sb = smem_u32(smatt);
    const uint32_t Qs = sb;
    const uint32_t Ks = sb + 16384;
    const uint32_t Vs = sb + 24576;

    const int t    = threadIdx.x;
    const int w    = t >> 5;
    const int lane = t & 31;
    const int rin  = lane & 15;
    const int hb   = lane >> 4;
    const int bh   = blockIdx.y;
    const int b    = bh >> 4;
    const int h    = bh & 15;
    const int n0   = blockIdx.x * 128;

    const size_t base = (size_t)b * SEQ * DIMD + (size_t)h * HD;

    {
        const __half* src = Qh + base + (size_t)(n0 + t) * DIMD;
        #pragma unroll
        for (int g = 0; g < 8; g++)
            st16(sw_addr(Qs, t, g), *(const uint4*)(src + g * 8));
    }
    __syncthreads();

    uint32_t qf[2][4][4];
    #pragma unroll
    for (int mi = 0; mi < 2; mi++)
        #pragma unroll
        for (int ks = 0; ks < 4; ks++)
            LDSM_X4(qf[mi][ks][0], qf[mi][ks][1], qf[mi][ks][2], qf[mi][ks][3],
                    sw_addr(Qs, w * 32 + mi * 16 + rin, 2 * ks + hb));

    float oacc[2][8][4];
    #pragma unroll
    for (int mi = 0; mi < 2; mi++)
        #pragma unroll
        for (int j = 0; j < 8; j++)
            #pragma unroll
            for (int q = 0; q < 4; q++) oacc[mi][j][q] = 0.0f;
    float lr[2][2] = {{0.0f, 0.0f}, {0.0f, 0.0f}};

    const int srow = t >> 1;
    const int scol = (t & 1) * 4;
    uint4 kpre[4], vpre[4];
    {
        const __half* kp = Kh + base + (size_t)srow * DIMD + scol * 8;
        const __half* vp = Vh + base + (size_t)srow * DIMD + scol * 8;
        #pragma unroll
        for (int g = 0; g < 4; g++) {
            kpre[g] = *(const uint4*)(kp + g * 8);
            vpre[g] = *(const uint4*)(vp + g * 8);
        }
    }

    for (int m0 = 0; m0 < SEQ; m0 += 64) {
        #pragma unroll
        for (int g = 0; g < 4; g++) {
            st16(sw_addr(Ks, srow, scol + g), kpre[g]);
            st16(sw_addr(Vs, srow, scol + g), vpre[g]);
        }
        __syncthreads();

        if (m0 + 64 < SEQ) {
            const __half* kp = Kh + base + (size_t)(m0 + 64 + srow) * DIMD + scol * 8;
            const __half* vp = Vh + base + (size_t)(m0 + 64 + srow) * DIMD + scol * 8;
            #pragma unroll
            for (int g = 0; g < 4; g++) {
                kpre[g] = *(const uint4*)(kp + g * 8);
                vpre[g] = *(const uint4*)(vp + g * 8);
            }
        }

        #pragma unroll
        for (int kh = 0; kh < 2; kh++) {
            float sacc[2][4][4];
            #pragma unroll
            for (int mi = 0; mi < 2; mi++)
                #pragma unroll
                for (int j = 0; j < 4; j++)
                    #pragma unroll
                    for (int q = 0; q < 4; q++) sacc[mi][j][q] = 0.0f;

            #pragma unroll
            for (int ks = 0; ks < 4; ks++) {
                uint32_t kb[2][4];
                #pragma unroll
                for (int pi = 0; pi < 2; pi++)
                    LDSM_X4(kb[pi][0], kb[pi][1], kb[pi][2], kb[pi][3],
                            sw_addr(Ks, kh * 32 + pi * 16 + rin, 2 * ks + hb));
                #pragma unroll
                for (int mi = 0; mi < 2; mi++)
                    #pragma unroll
                    for (int pi = 0; pi < 2; pi++) {
                        MMA_F16(sacc[mi][2 * pi],     qf[mi][ks], kb[pi][0], kb[pi][2]);
                        MMA_F16(sacc[mi][2 * pi + 1], qf[mi][ks], kb[pi][1], kb[pi][3]);
                    }
            }

            uint32_t pf[2][4][2];
            #pragma unroll
            for (int mi = 0; mi < 2; mi++)
                #pragma unroll
                for (int j = 0; j < 4; j++) {
                    float p0 = __expf(sacc[mi][j][0] * 0.03125f);
                    float p1 = __expf(sacc[mi][j][1] * 0.03125f);
                    float p2 = __expf(sacc[mi][j][2] * 0.03125f);
                    float p3 = __expf(sacc[mi][j][3] * 0.03125f);
                    lr[mi][0] += p0 + p1;
                    lr[mi][1] += p2 + p3;
                    pf[mi][j][0] = pkhf(p0, p1);
                    pf[mi][j][1] = pkhf(p2, p3);
                }

            #pragma unroll
            for (int ks2 = 0; ks2 < 2; ks2++) {
                uint32_t pa[2][4];
                #pragma unroll
                for (int mi = 0; mi < 2; mi++) {
                    pa[mi][0] = pf[mi][2 * ks2][0];     pa[mi][1] = pf[mi][2 * ks2][1];
                    pa[mi][2] = pf[mi][2 * ks2 + 1][0]; pa[mi][3] = pf[mi][2 * ks2 + 1][1];
                }
                #pragma unroll
                for (int pi = 0; pi < 4; pi++) {
                    uint32_t vb0, vb1, vb2, vb3;
                    LDSM_X4_T(vb0, vb1, vb2, vb3,
                              sw_addr(Vs, kh * 32 + ks2 * 16 + rin, 2 * pi + hb));
                    #pragma unroll
                    for (int mi = 0; mi < 2; mi++) {
                        MMA_F16(oacc[mi][2 * pi],     pa[mi], vb0, vb1);
                        MMA_F16(oacc[mi][2 * pi + 1], pa[mi], vb2, vb3);
                    }
                }
            }
        }
        __syncthreads();
    }

    #pragma unroll
    for (int mi = 0; mi < 2; mi++) {
        lr[mi][0] += __shfl_xor_sync(0xffffffffu, lr[mi][0], 1);
        lr[mi][0] += __shfl_xor_sync(0xffffffffu, lr[mi][0], 2);
        lr[mi][1] += __shfl_xor_sync(0xffffffffu, lr[mi][1], 1);
        lr[mi][1] += __shfl_xor_sync(0xffffffffu, lr[mi][1], 2);
        const float inv0 = 1.0f / lr[mi][0];
        const float inv1 = 1.0f / lr[mi][1];

        const int r0 = n0 + w * 32 + mi * 16 + (lane >> 2);
        const int r1 = r0 + 8;
        #pragma unroll
        for (int j = 0; j < 8; j++) {
            const int col = j * 8 + (lane & 3) * 2;
            float2 q0 = *(const float2*)&Qp[base + (size_t)r0 * DIMD + col];
            float2 q1 = *(const float2*)&Qp[base + (size_t)r1 * DIMD + col];
            float o00 = oacc[mi][j][0] * inv0 + q0.x;
            float o01 = oacc[mi][j][1] * inv0 + q0.y;
            float o10 = oacc[mi][j][2] * inv1 + q1.x;
            float o11 = oacc[mi][j][3] * inv1 + q1.y;
            *(float2*)&Oh[base + (size_t)r0 * DIMD + col] = make_float2(o00, o01);
            *(float2*)&Oh[base + (size_t)r1 * DIMD + col] = make_float2(o10, o11);
            *(uint32_t*)&OhH[base + (size_t)r0 * DIMD + col] = pkhf(o00, o01);
            *(uint32_t*)&OhH[base + (size_t)r1 * DIMD + col] = pkhf(o10, o11);
        }
    }
}

// ================================================================================
extern "C" void kernel_launch(void* const* d_in, const int* in_sizes, int n_in,
                              void* d_out, int out_size)
{
    const float* Q  = (const float*)d_in[0];
    const float* K  = (const float*)d_in[1];
    const float* Wq = (const float*)d_in[2];
    const float* bq = (const float*)d_in[3];
    const float* Wk = (const float*)d_in[4];
    const float* bk = (const float*)d_in[5];
    const float* Wv = (const float*)d_in[6];
    const float* bv = (const float*)d_in[7];
    const float* Wo = (const float*)d_in[8];
    const float* bo = (const float*)d_in[9];
    float* out = (float*)d_out;

    float *Qp, *Oh;
    __half *Qh, *Kh, *Vh, *OhH;
    cudaGetSymbolAddress((void**)&Qp,  g_Qp);
    cudaGetSymbolAddress((void**)&Oh,  g_Oh);
    cudaGetSymbolAddress((void**)&Qh,  g_Qh);
    cudaGetSymbolAddress((void**)&Kh,  g_Kh);
    cudaGetSymbolAddress((void**)&Vh,  g_Vh);
    cudaGetSymbolAddress((void**)&OhH, g_OhH);

    cudaFuncSetAttribute(attn_mma,
                         cudaFuncAttributeMaxDynamicSharedMemorySize, ATT_SMEM);
    cudaFuncSetAttribute(gemm_proj3,
                         cudaFuncAttributeMaxDynamicSharedMemorySize, GEMM_SMEM);
    cudaFuncSetAttribute(gemm_out,
                         cudaFuncAttributeMaxDynamicSharedMemorySize, GEMM_SMEM);

    gemm_proj3<<<dim3(8, 64, 3), 256, GEMM_SMEM>>>(
        Q, K, Wq, Wk, Wv, bq, bk, bv, Qp, Qh, Kh, Vh);
    attn_mma<<<dim3(16, 64), 128, ATT_SMEM>>>(Qh, Kh, Vh, Qp, Oh, OhH);
    gemm_out<<<dim3(8, 64), 256, GEMM_SMEM>>>(OhH, Wo, bo, Oh, out);
}

// round 15
// speedup vs baseline: 1.2285x; 1.2285x over previous
#include <cuda_runtime.h>
#include <cuda_fp16.h>
#include <cstdint>
#include <cstddef>

#define DIMD   1024
#define TT     8192     // B*N = B*M rows
#define HD     64       // head dim
#define SEQ    2048

// ---------------- scratch ----------------
__device__ float  g_Qp [TT * DIMD];   // fp32 Q projection (residual)
__device__ float  g_Oh [TT * DIMD];   // fp32 attention out (residual for final gemm)
__device__ __half g_Qh [TT * DIMD];
__device__ __half g_Kh [TT * DIMD];
__device__ __half g_Vh [TT * DIMD];
__device__ __half g_OhH[TT * DIMD];
__device__ __half g_XqH[TT * DIMD];   // fp16 input Q
__device__ __half g_XkH[TT * DIMD];   // fp16 input K
__device__ __half g_WqH[DIMD * DIMD];
__device__ __half g_WkH[DIMD * DIMD];
__device__ __half g_WvH[DIMD * DIMD];
__device__ __half g_WoH[DIMD * DIMD];

// =========================== helpers =================================
__device__ __forceinline__ uint32_t smem_u32(const void* p) {
    uint32_t a;
    asm("{ .reg .u64 t; cvta.to.shared.u64 t, %1; cvt.u32.u64 %0, t; }"
        : "=r"(a) : "l"(p));
    return a;
}

#define LDSM_X4(R0, R1, R2, R3, addr) \
    asm volatile("ldmatrix.sync.aligned.m8n8.x4.shared.b16 {%0,%1,%2,%3}, [%4];" \
                 : "=r"(R0), "=r"(R1), "=r"(R2), "=r"(R3) : "r"(addr))

#define LDSM_X4_T(R0, R1, R2, R3, addr) \
    asm volatile("ldmatrix.sync.aligned.m8n8.x4.trans.shared.b16 {%0,%1,%2,%3}, [%4];" \
                 : "=r"(R0), "=r"(R1), "=r"(R2), "=r"(R3) : "r"(addr))

#define MMA_F16(c, a, b0, b1) \
    asm volatile("mma.sync.aligned.m16n8k16.row.col.f32.f16.f16.f32 " \
                 "{%0,%1,%2,%3}, {%4,%5,%6,%7}, {%8,%9}, {%0,%1,%2,%3};" \
                 : "+f"((c)[0]), "+f"((c)[1]), "+f"((c)[2]), "+f"((c)[3]) \
                 : "r"((a)[0]), "r"((a)[1]), "r"((a)[2]), "r"((a)[3]), \
                   "r"(b0), "r"(b1))

#define CP_ASYNC16(smem, gptr) \
    asm volatile("cp.async.cg.shared.global [%0], [%1], 16;" \
                 :: "r"(smem), "l"(gptr) : "memory")
#define CP_COMMIT() asm volatile("cp.async.commit_group;" ::: "memory")
#define CP_WAIT0()  asm volatile("cp.async.wait_group 0;" ::: "memory")

__device__ __forceinline__ uint32_t pkhf(float lo, float hi) {
    uint32_t d;
    asm("cvt.rn.f16x2.f32 %0, %1, %2;" : "=r"(d) : "f"(hi), "f"(lo));
    return d;
}

// swizzled smem address: 128B rows, 8 chunks of 16B, chunk c XOR (r&7)
__device__ __forceinline__ uint32_t sw_addr(uint32_t base, int r, int c) {
    return base + (uint32_t)(r * 128) + (uint32_t)(((c ^ (r & 7)) & 7) << 4);
}

__device__ __forceinline__ void st16(uint32_t a, uint4 v) {
    asm volatile("st.shared.v4.b32 [%0], {%1,%2,%3,%4};"
                 :: "r"(a), "r"(v.x), "r"(v.y), "r"(v.z), "r"(v.w));
}

// ================================================================================
// fp32 -> fp16 conversion (elementwise, 8 per thread; rounding identical to the
// previous in-loop staging conversion -> bit-identical results)
// ================================================================================
__global__ void __launch_bounds__(256)
f2h_kernel(const float* __restrict__ in, __half* __restrict__ out, int n)
{
    int i = (blockIdx.x * 256 + threadIdx.x) * 8;
    if (i >= n) return;
    float4 a = *(const float4*)(in + i);
    float4 b = *(const float4*)(in + i + 4);
    uint4 o;
    o.x = pkhf(a.x, a.y); o.y = pkhf(a.z, a.w);
    o.z = pkhf(b.x, b.y); o.w = pkhf(b.z, b.w);
    *(uint4*)(out + i) = o;
}

// ================================================================================
// All-fp16 GEMM, cp.async staging, CTA tile 128x256, warp tile 64x64, BK=64.
// 8 warps (2m x 4n). MMA:LDSM = 4:1.
//   MODE 0: fp16 CH only
//   MODE 1: fp16 CH + fp32 C32
//   MODE 2: fp32 C32 = R + relu(acc + bias)
// smem: per buffer A 128x64 fp16 (16KB) + B 256x64 fp16 (32KB); double buffered.
// ================================================================================
#define GEMM_SMEM (2 * 49152)

template <int MODE>
__global__ void __launch_bounds__(256)
gemm16(const __half* __restrict__ X, const __half* __restrict__ W,
       const float* __restrict__ bias, const float* __restrict__ R,
       float* __restrict__ C32, __half* __restrict__ CH)
{
    extern __shared__ char sm[];
    const uint32_t sb = smem_u32(sm);

    const int t    = threadIdx.x;
    const int w    = t >> 5;
    const int lane = t & 31;
    const int wm   = w >> 2;     // 0..1 : 64-row slab
    const int wn   = w & 3;      // 0..3 : 64-col slab
    const int bn   = blockIdx.x;
    const int bm   = blockIdx.y;
    const int rin  = lane & 15;
    const int hb   = lane >> 4;

    float acc[4][8][4];
    #pragma unroll
    for (int mi = 0; mi < 4; mi++)
        #pragma unroll
        for (int ni = 0; ni < 8; ni++)
            #pragma unroll
            for (int q = 0; q < 4; q++) acc[mi][ni][q] = 0.0f;

    // stage chunk ch into buffer buf via cp.async (A: 4 chunks/thr, B: 8)
    auto stage = [&](int ch, uint32_t buf) {
        const int k0 = ch * 64;
        #pragma unroll
        for (int s = 0; s < 4; s++) {
            int idx = t + 256 * s;
            int r = idx >> 3, c = idx & 7;
            CP_ASYNC16(sw_addr(buf, r, c),
                       X + (size_t)(bm * 128 + r) * DIMD + k0 + c * 8);
        }
        #pragma unroll
        for (int s = 0; s < 8; s++) {
            int idx = t + 256 * s;
            int r = idx >> 3, c = idx & 7;
            CP_ASYNC16(sw_addr(buf + 16384u, r, c),
                       W + (size_t)(bn * 256 + r) * DIMD + k0 + c * 8);
        }
        CP_COMMIT();
    };

    stage(0, sb);

    for (int ch = 0; ch < 16; ch++) {
        const uint32_t buf = sb + (uint32_t)(ch & 1) * 49152u;
        CP_WAIT0();
        __syncthreads();
        if (ch + 1 < 16)
            stage(ch + 1, sb + (uint32_t)((ch + 1) & 1) * 49152u);

        #pragma unroll
        for (int ks = 0; ks < 4; ks++) {
            const int chi = 2 * ks + hb;
            uint32_t afr[4][4];
            #pragma unroll
            for (int mi = 0; mi < 4; mi++)
                LDSM_X4(afr[mi][0], afr[mi][1], afr[mi][2], afr[mi][3],
                        sw_addr(buf, wm * 64 + mi * 16 + rin, chi));
            uint32_t bf[4][4];
            #pragma unroll
            for (int pi = 0; pi < 4; pi++)
                LDSM_X4(bf[pi][0], bf[pi][1], bf[pi][2], bf[pi][3],
                        sw_addr(buf + 16384u, wn * 64 + pi * 16 + rin, chi));
            #pragma unroll
            for (int mi = 0; mi < 4; mi++)
                #pragma unroll
                for (int pi = 0; pi < 4; pi++) {
                    MMA_F16(acc[mi][2 * pi],     afr[mi], bf[pi][0], bf[pi][2]);
                    MMA_F16(acc[mi][2 * pi + 1], afr[mi], bf[pi][1], bf[pi][3]);
                }
        }
    }

    // ------------------------- epilogue -------------------------
    const int rbase = bm * 128 + wm * 64;
    const int cbase = bn * 256 + wn * 64;
    float bb[8][2];
    #pragma unroll
    for (int ni = 0; ni < 8; ni++) {
        int c0 = cbase + ni * 8 + (lane & 3) * 2;
        bb[ni][0] = bias[c0];
        bb[ni][1] = bias[c0 + 1];
    }

    #pragma unroll
    for (int mi = 0; mi < 4; mi++) {
        #pragma unroll
        for (int ni = 0; ni < 8; ni++) {
            int r0 = rbase + mi * 16 + (lane >> 2);
            int c0 = cbase + ni * 8 + (lane & 3) * 2;
            float o0 = acc[mi][ni][0] + bb[ni][0];
            float o1 = acc[mi][ni][1] + bb[ni][1];
            float o2 = acc[mi][ni][2] + bb[ni][0];
            float o3 = acc[mi][ni][3] + bb[ni][1];
            if (MODE == 2) {
                float2 ra = *(const float2*)&R[(size_t)r0 * DIMD + c0];
                float2 rb = *(const float2*)&R[(size_t)(r0 + 8) * DIMD + c0];
                o0 = fmaxf(o0, 0.0f) + ra.x;
                o1 = fmaxf(o1, 0.0f) + ra.y;
                o2 = fmaxf(o2, 0.0f) + rb.x;
                o3 = fmaxf(o3, 0.0f) + rb.y;
                *(float2*)&C32[(size_t)r0 * DIMD + c0]       = make_float2(o0, o1);
                *(float2*)&C32[(size_t)(r0 + 8) * DIMD + c0] = make_float2(o2, o3);
            } else {
                *(uint32_t*)&CH[(size_t)r0 * DIMD + c0]       = pkhf(o0, o1);
                *(uint32_t*)&CH[(size_t)(r0 + 8) * DIMD + c0] = pkhf(o2, o3);
                if (MODE == 1) {
                    *(float2*)&C32[(size_t)r0 * DIMD + c0]       = make_float2(o0, o1);
                    *(float2*)&C32[(size_t)(r0 + 8) * DIMD + c0] = make_float2(o2, o3);
                }
            }
        }
    }
}

// ================================================================================
// Tensor-core flash attention (R13-proven, unchanged): Br=128, Bc=64, d=64,
// 4 warps, 32 Q-rows/warp, keys in 32-wide halves. fp16 in, fp32 accum.
// ================================================================================
#define ATT_SMEM (16384 + 8192 + 8192)

__global__ void __launch_bounds__(128, 2)
attn_mma(const __half* __restrict__ Qh, const __half* __restrict__ Kh,
         const __half* __restrict__ Vh, const float* __restrict__ Qp,
         float* __restrict__ Oh, __half* __restrict__ OhH)
{
    extern __shared__ char smatt[];
    const uint32_t sb = smem_u32(smatt);
    const uint32_t Qs = sb;
    const uint32_t Ks = sb + 16384;
    const uint32_t Vs = sb + 24576;

    const int t    = threadIdx.x;
    const int w    = t >> 5;
    const int lane = t & 31;
    const int rin  = lane & 15;
    const int hb   = lane >> 4;
    const int bh   = blockIdx.y;
    const int b    = bh >> 4;
    const int h    = bh & 15;
    const int n0   = blockIdx.x * 128;

    const size_t base = (size_t)b * SEQ * DIMD + (size_t)h * HD;

    {
        const __half* src = Qh + base + (size_t)(n0 + t) * DIMD;
        #pragma unroll
        for (int g = 0; g < 8; g++)
            st16(sw_addr(Qs, t, g), *(const uint4*)(src + g * 8));
    }
    __syncthreads();

    uint32_t qf[2][4][4];
    #pragma unroll
    for (int mi = 0; mi < 2; mi++)
        #pragma unroll
        for (int ks = 0; ks < 4; ks++)
            LDSM_X4(qf[mi][ks][0], qf[mi][ks][1], qf[mi][ks][2], qf[mi][ks][3],
                    sw_addr(Qs, w * 32 + mi * 16 + rin, 2 * ks + hb));

    float oacc[2][8][4];
    #pragma unroll
    for (int mi = 0; mi < 2; mi++)
        #pragma unroll
        for (int j = 0; j < 8; j++)
            #pragma unroll
            for (int q = 0; q < 4; q++) oacc[mi][j][q] = 0.0f;
    float lr[2][2] = {{0.0f, 0.0f}, {0.0f, 0.0f}};

    const int srow = t >> 1;
    const int scol = (t & 1) * 4;
    uint4 kpre[4], vpre[4];
    {
        const __half* kp = Kh + base + (size_t)srow * DIMD + scol * 8;
        const __half* vp = Vh + base + (size_t)srow * DIMD + scol * 8;
        #pragma unroll
        for (int g = 0; g < 4; g++) {
            kpre[g] = *(const uint4*)(kp + g * 8);
            vpre[g] = *(const uint4*)(vp + g * 8);
        }
    }

    for (int m0 = 0; m0 < SEQ; m0 += 64) {
        #pragma unroll
        for (int g = 0; g < 4; g++) {
            st16(sw_addr(Ks, srow, scol + g), kpre[g]);
            st16(sw_addr(Vs, srow, scol + g), vpre[g]);
        }
        __syncthreads();

        if (m0 + 64 < SEQ) {
            const __half* kp = Kh + base + (size_t)(m0 + 64 + srow) * DIMD + scol * 8;
            const __half* vp = Vh + base + (size_t)(m0 + 64 + srow) * DIMD + scol * 8;
            #pragma unroll
            for (int g = 0; g < 4; g++) {
                kpre[g] = *(const uint4*)(kp + g * 8);
                vpre[g] = *(const uint4*)(vp + g * 8);
            }
        }

        #pragma unroll
        for (int kh = 0; kh < 2; kh++) {
            float sacc[2][4][4];
            #pragma unroll
            for (int mi = 0; mi < 2; mi++)
                #pragma unroll
                for (int j = 0; j < 4; j++)
                    #pragma unroll
                    for (int q = 0; q < 4; q++) sacc[mi][j][q] = 0.0f;

            #pragma unroll
            for (int ks = 0; ks < 4; ks++) {
                uint32_t kb[2][4];
                #pragma unroll
                for (int pi = 0; pi < 2; pi++)
                    LDSM_X4(kb[pi][0], kb[pi][1], kb[pi][2], kb[pi][3],
                            sw_addr(Ks, kh * 32 + pi * 16 + rin, 2 * ks + hb));
                #pragma unroll
                for (int mi = 0; mi < 2; mi++)
                    #pragma unroll
                    for (int pi = 0; pi < 2; pi++) {
                        MMA_F16(sacc[mi][2 * pi],     qf[mi][ks], kb[pi][0], kb[pi][2]);
                        MMA_F16(sacc[mi][2 * pi + 1], qf[mi][ks], kb[pi][1], kb[pi][3]);
                    }
            }

            uint32_t pf[2][4][2];
            #pragma unroll
            for (int mi = 0; mi < 2; mi++)
                #pragma unroll
                for (int j = 0; j < 4; j++) {
                    float p0 = __expf(sacc[mi][j][0] * 0.03125f);
                    float p1 = __expf(sacc[mi][j][1] * 0.03125f);
                    float p2 = __expf(sacc[mi][j][2] * 0.03125f);
                    float p3 = __expf(sacc[mi][j][3] * 0.03125f);
                    lr[mi][0] += p0 + p1;
                    lr[mi][1] += p2 + p3;
                    pf[mi][j][0] = pkhf(p0, p1);
                    pf[mi][j][1] = pkhf(p2, p3);
                }

            #pragma unroll
            for (int ks2 = 0; ks2 < 2; ks2++) {
                uint32_t pa[2][4];
                #pragma unroll
                for (int mi = 0; mi < 2; mi++) {
                    pa[mi][0] = pf[mi][2 * ks2][0];     pa[mi][1] = pf[mi][2 * ks2][1];
                    pa[mi][2] = pf[mi][2 * ks2 + 1][0]; pa[mi][3] = pf[mi][2 * ks2 + 1][1];
                }
                #pragma unroll
                for (int pi = 0; pi < 4; pi++) {
                    uint32_t vb0, vb1, vb2, vb3;
                    LDSM_X4_T(vb0, vb1, vb2, vb3,
                              sw_addr(Vs, kh * 32 + ks2 * 16 + rin, 2 * pi + hb));
                    #pragma unroll
                    for (int mi = 0; mi < 2; mi++) {
                        MMA_F16(oacc[mi][2 * pi],     pa[mi], vb0, vb1);
                        MMA_F16(oacc[mi][2 * pi + 1], pa[mi], vb2, vb3);
                    }
                }
            }
        }
        __syncthreads();
    }

    #pragma unroll
    for (int mi = 0; mi < 2; mi++) {
        lr[mi][0] += __shfl_xor_sync(0xffffffffu, lr[mi][0], 1);
        lr[mi][0] += __shfl_xor_sync(0xffffffffu, lr[mi][0], 2);
        lr[mi][1] += __shfl_xor_sync(0xffffffffu, lr[mi][1], 1);
        lr[mi][1] += __shfl_xor_sync(0xffffffffu, lr[mi][1], 2);
        const float inv0 = 1.0f / lr[mi][0];
        const float inv1 = 1.0f / lr[mi][1];

        const int r0 = n0 + w * 32 + mi * 16 + (lane >> 2);
        const int r1 = r0 + 8;
        #pragma unroll
        for (int j = 0; j < 8; j++) {
            const int col = j * 8 + (lane & 3) * 2;
            float2 q0 = *(const float2*)&Qp[base + (size_t)r0 * DIMD + col];
            float2 q1 = *(const float2*)&Qp[base + (size_t)r1 * DIMD + col];
            float o00 = oacc[mi][j][0] * inv0 + q0.x;
            float o01 = oacc[mi][j][1] * inv0 + q0.y;
            float o10 = oacc[mi][j][2] * inv1 + q1.x;
            float o11 = oacc[mi][j][3] * inv1 + q1.y;
            *(float2*)&Oh[base + (size_t)r0 * DIMD + col] = make_float2(o00, o01);
            *(float2*)&Oh[base + (size_t)r1 * DIMD + col] = make_float2(o10, o11);
            *(uint32_t*)&OhH[base + (size_t)r0 * DIMD + col] = pkhf(o00, o01);
            *(uint32_t*)&OhH[base + (size_t)r1 * DIMD + col] = pkhf(o10, o11);
        }
    }
}

// ================================================================================
extern "C" void kernel_launch(void* const* d_in, const int* in_sizes, int n_in,
                              void* d_out, int out_size)
{
    const float* Q  = (const float*)d_in[0];
    const float* K  = (const float*)d_in[1];
    const float* Wq = (const float*)d_in[2];
    const float* bq = (const float*)d_in[3];
    const float* Wk = (const float*)d_in[4];
    const float* bk = (const float*)d_in[5];
    const float* Wv = (const float*)d_in[6];
    const float* bv = (const float*)d_in[7];
    const float* Wo = (const float*)d_in[8];
    const float* bo = (const float*)d_in[9];
    float* out = (float*)d_out;

    float *Qp, *Oh;
    __half *Qh, *Kh, *Vh, *OhH, *XqH, *XkH, *WqH, *WkH, *WvH, *WoH;
    cudaGetSymbolAddress((void**)&Qp,  g_Qp);
    cudaGetSymbolAddress((void**)&Oh,  g_Oh);
    cudaGetSymbolAddress((void**)&Qh,  g_Qh);
    cudaGetSymbolAddress((void**)&Kh,  g_Kh);
    cudaGetSymbolAddress((void**)&Vh,  g_Vh);
    cudaGetSymbolAddress((void**)&OhH, g_OhH);
    cudaGetSymbolAddress((void**)&XqH, g_XqH);
    cudaGetSymbolAddress((void**)&XkH, g_XkH);
    cudaGetSymbolAddress((void**)&WqH, g_WqH);
    cudaGetSymbolAddress((void**)&WkH, g_WkH);
    cudaGetSymbolAddress((void**)&WvH, g_WvH);
    cudaGetSymbolAddress((void**)&WoH, g_WoH);

    cudaFuncSetAttribute(attn_mma,
                         cudaFuncAttributeMaxDynamicSharedMemorySize, ATT_SMEM);
    cudaFuncSetAttribute(gemm16<0>,
                         cudaFuncAttributeMaxDynamicSharedMemorySize, GEMM_SMEM);
    cudaFuncSetAttribute(gemm16<1>,
                         cudaFuncAttributeMaxDynamicSharedMemorySize, GEMM_SMEM);
    cudaFuncSetAttribute(gemm16<2>,
                         cudaFuncAttributeMaxDynamicSharedMemorySize, GEMM_SMEM);

    // one-time fp16 pre-conversion (bit-identical rounding to in-loop cvt)
    const int nX = TT * DIMD, nW = DIMD * DIMD;
    f2h_kernel<<<nX / 2048, 256>>>(Q,  XqH, nX);
    f2h_kernel<<<nX / 2048, 256>>>(K,  XkH, nX);
    f2h_kernel<<<nW / 2048, 256>>>(Wq, WqH, nW);
    f2h_kernel<<<nW / 2048, 256>>>(Wk, WkH, nW);
    f2h_kernel<<<nW / 2048, 256>>>(Wv, WvH, nW);
    f2h_kernel<<<nW / 2048, 256>>>(Wo, WoH, nW);

    dim3 gg(DIMD / 256, TT / 128);   // (4, 64)
    gemm16<1><<<gg, 256, GEMM_SMEM>>>(XqH, WqH, bq, nullptr, Qp, Qh);
    gemm16<0><<<gg, 256, GEMM_SMEM>>>(XkH, WkH, bk, nullptr, nullptr, Kh);
    gemm16<0><<<gg, 256, GEMM_SMEM>>>(XkH, WvH, bv, nullptr, nullptr, Vh);
    attn_mma<<<dim3(16, 64), 128, ATT_SMEM>>>(Qh, Kh, Vh, Qp, Oh, OhH);
    gemm16<2><<<gg, 256, GEMM_SMEM>>>(OhH, WoH, bo, Oh, out, nullptr);
}

// round 16
// speedup vs baseline: 1.2718x; 1.0353x over previous
#include <cuda_runtime.h>
#include <cuda_fp16.h>
#include <cstdint>
#include <cstddef>

#define DIMD   1024
#define TT     8192     // B*N = B*M rows
#define HD     64       // head dim
#define SEQ    2048

// ---------------- scratch ----------------
__device__ __half g_Qh [TT * DIMD];
__device__ __half g_Kh [TT * DIMD];
__device__ __half g_Vh [TT * DIMD];
__device__ __half g_OhH[TT * DIMD];
__device__ __half g_XqH[TT * DIMD];
__device__ __half g_XkH[TT * DIMD];
__device__ __half g_WqH[DIMD * DIMD];
__device__ __half g_WkH[DIMD * DIMD];
__device__ __half g_WvH[DIMD * DIMD];
__device__ __half g_WoH[DIMD * DIMD];

// =========================== helpers =================================
__device__ __forceinline__ uint32_t smem_u32(const void* p) {
    uint32_t a;
    asm("{ .reg .u64 t; cvta.to.shared.u64 t, %1; cvt.u32.u64 %0, t; }"
        : "=r"(a) : "l"(p));
    return a;
}

#define LDSM_X4(R0, R1, R2, R3, addr) \
    asm volatile("ldmatrix.sync.aligned.m8n8.x4.shared.b16 {%0,%1,%2,%3}, [%4];" \
                 : "=r"(R0), "=r"(R1), "=r"(R2), "=r"(R3) : "r"(addr))

#define LDSM_X4_T(R0, R1, R2, R3, addr) \
    asm volatile("ldmatrix.sync.aligned.m8n8.x4.trans.shared.b16 {%0,%1,%2,%3}, [%4];" \
                 : "=r"(R0), "=r"(R1), "=r"(R2), "=r"(R3) : "r"(addr))

#define MMA_F16(c, a, b0, b1) \
    asm volatile("mma.sync.aligned.m16n8k16.row.col.f32.f16.f16.f32 " \
                 "{%0,%1,%2,%3}, {%4,%5,%6,%7}, {%8,%9}, {%0,%1,%2,%3};" \
                 : "+f"((c)[0]), "+f"((c)[1]), "+f"((c)[2]), "+f"((c)[3]) \
                 : "r"((a)[0]), "r"((a)[1]), "r"((a)[2]), "r"((a)[3]), \
                   "r"(b0), "r"(b1))

#define CP_ASYNC16(smem, gptr) \
    asm volatile("cp.async.cg.shared.global [%0], [%1], 16;" \
                 :: "r"(smem), "l"(gptr) : "memory")
#define CP_COMMIT() asm volatile("cp.async.commit_group;" ::: "memory")
#define CP_WAIT0()  asm volatile("cp.async.wait_group 0;" ::: "memory")

__device__ __forceinline__ uint32_t pkhf(float lo, float hi) {
    uint32_t d;
    asm("cvt.rn.f16x2.f32 %0, %1, %2;" : "=r"(d) : "f"(hi), "f"(lo));
    return d;
}

// swizzled smem address: 128B rows, 8 chunks of 16B, chunk c XOR (r&7)
__device__ __forceinline__ uint32_t sw_addr(uint32_t base, int r, int c) {
    return base + (uint32_t)(r * 128) + (uint32_t)(((c ^ (r & 7)) & 7) << 4);
}

__device__ __forceinline__ void st16(uint32_t a, uint4 v) {
    asm volatile("st.shared.v4.b32 [%0], {%1,%2,%3,%4};"
                 :: "r"(a), "r"(v.x), "r"(v.y), "r"(v.z), "r"(v.w));
}

// ================================================================================
// fp32 -> fp16 conversion (elementwise, 8 per thread)
// ================================================================================
__global__ void __launch_bounds__(256)
f2h_kernel(const float* __restrict__ in, __half* __restrict__ out, int n)
{
    int i = (blockIdx.x * 256 + threadIdx.x) * 8;
    if (i >= n) return;
    float4 a = *(const float4*)(in + i);
    float4 b = *(const float4*)(in + i + 4);
    uint4 o;
    o.x = pkhf(a.x, a.y); o.y = pkhf(a.z, a.w);
    o.z = pkhf(b.x, b.y); o.w = pkhf(b.z, b.w);
    *(uint4*)(out + i) = o;
}

// ================================================================================
// All-fp16 GEMM, cp.async staging, CTA tile 128x256, warp tile 64x64, BK=64.
// 8 warps (2m x 4n). MODE 0: fp16 CH.  MODE 2: fp32 C32 = Rh + relu(acc+bias).
// ================================================================================
#define GEMM_SMEM (2 * 49152)

template <int MODE>
__global__ void __launch_bounds__(256)
gemm16(const __half* __restrict__ X, const __half* __restrict__ W,
       const float* __restrict__ bias, const __half* __restrict__ Rh,
       float* __restrict__ C32, __half* __restrict__ CH)
{
    extern __shared__ char sm[];
    const uint32_t sb = smem_u32(sm);

    const int t    = threadIdx.x;
    const int w    = t >> 5;
    const int lane = t & 31;
    const int wm   = w >> 2;
    const int wn   = w & 3;
    const int bn   = blockIdx.x;
    const int bm   = blockIdx.y;
    const int rin  = lane & 15;
    const int hb   = lane >> 4;

    float acc[4][8][4];
    #pragma unroll
    for (int mi = 0; mi < 4; mi++)
        #pragma unroll
        for (int ni = 0; ni < 8; ni++)
            #pragma unroll
            for (int q = 0; q < 4; q++) acc[mi][ni][q] = 0.0f;

    auto stage = [&](int ch, uint32_t buf) {
        const int k0 = ch * 64;
        #pragma unroll
        for (int s = 0; s < 4; s++) {
            int idx = t + 256 * s;
            int r = idx >> 3, c = idx & 7;
            CP_ASYNC16(sw_addr(buf, r, c),
                       X + (size_t)(bm * 128 + r) * DIMD + k0 + c * 8);
        }
        #pragma unroll
        for (int s = 0; s < 8; s++) {
            int idx = t + 256 * s;
            int r = idx >> 3, c = idx & 7;
            CP_ASYNC16(sw_addr(buf + 16384u, r, c),
                       W + (size_t)(bn * 256 + r) * DIMD + k0 + c * 8);
        }
        CP_COMMIT();
    };

    stage(0, sb);

    for (int ch = 0; ch < 16; ch++) {
        const uint32_t buf = sb + (uint32_t)(ch & 1) * 49152u;
        CP_WAIT0();
        __syncthreads();
        if (ch + 1 < 16)
            stage(ch + 1, sb + (uint32_t)((ch + 1) & 1) * 49152u);

        #pragma unroll
        for (int ks = 0; ks < 4; ks++) {
            const int chi = 2 * ks + hb;
            uint32_t afr[4][4];
            #pragma unroll
            for (int mi = 0; mi < 4; mi++)
                LDSM_X4(afr[mi][0], afr[mi][1], afr[mi][2], afr[mi][3],
                        sw_addr(buf, wm * 64 + mi * 16 + rin, chi));
            uint32_t bf[4][4];
            #pragma unroll
            for (int pi = 0; pi < 4; pi++)
                LDSM_X4(bf[pi][0], bf[pi][1], bf[pi][2], bf[pi][3],
                        sw_addr(buf + 16384u, wn * 64 + pi * 16 + rin, chi));
            #pragma unroll
            for (int mi = 0; mi < 4; mi++)
                #pragma unroll
                for (int pi = 0; pi < 4; pi++) {
                    MMA_F16(acc[mi][2 * pi],     afr[mi], bf[pi][0], bf[pi][2]);
                    MMA_F16(acc[mi][2 * pi + 1], afr[mi], bf[pi][1], bf[pi][3]);
                }
        }
    }

    // ------------------------- epilogue -------------------------
    const int rbase = bm * 128 + wm * 64;
    const int cbase = bn * 256 + wn * 64;
    float bb[8][2];
    #pragma unroll
    for (int ni = 0; ni < 8; ni++) {
        int c0 = cbase + ni * 8 + (lane & 3) * 2;
        bb[ni][0] = bias[c0];
        bb[ni][1] = bias[c0 + 1];
    }

    #pragma unroll
    for (int mi = 0; mi < 4; mi++) {
        #pragma unroll
        for (int ni = 0; ni < 8; ni++) {
            int r0 = rbase + mi * 16 + (lane >> 2);
            int c0 = cbase + ni * 8 + (lane & 3) * 2;
            float o0 = acc[mi][ni][0] + bb[ni][0];
            float o1 = acc[mi][ni][1] + bb[ni][1];
            float o2 = acc[mi][ni][2] + bb[ni][0];
            float o3 = acc[mi][ni][3] + bb[ni][1];
            if (MODE == 2) {
                __half2 ra = *(const __half2*)&Rh[(size_t)r0 * DIMD + c0];
                __half2 rb = *(const __half2*)&Rh[(size_t)(r0 + 8) * DIMD + c0];
                float2 raf = __half22float2(ra);
                float2 rbf = __half22float2(rb);
                o0 = fmaxf(o0, 0.0f) + raf.x;
                o1 = fmaxf(o1, 0.0f) + raf.y;
                o2 = fmaxf(o2, 0.0f) + rbf.x;
                o3 = fmaxf(o3, 0.0f) + rbf.y;
                *(float2*)&C32[(size_t)r0 * DIMD + c0]       = make_float2(o0, o1);
                *(float2*)&C32[(size_t)(r0 + 8) * DIMD + c0] = make_float2(o2, o3);
            } else {
                *(uint32_t*)&CH[(size_t)r0 * DIMD + c0]       = pkhf(o0, o1);
                *(uint32_t*)&CH[(size_t)(r0 + 8) * DIMD + c0] = pkhf(o2, o3);
            }
        }
    }
}

// ================================================================================
// Tensor-core flash attention: Br=128, Bc=64, d=64, 4 warps, 32 Q-rows/warp,
// keys in 32-wide halves. cp.async double-buffered K/V staging.
// Q-residual read from smem Qs. Writes fp16 OhH only.
// ================================================================================
#define ATT_SMEM (16384 + 2 * 16384)

__global__ void __launch_bounds__(128, 2)
attn_mma(const __half* __restrict__ Qh, const __half* __restrict__ Kh,
         const __half* __restrict__ Vh, __half* __restrict__ OhH)
{
    extern __shared__ char smatt[];
    const uint32_t sb = smem_u32(smatt);
    const uint32_t Qs = sb;

    const int t    = threadIdx.x;
    const int w    = t >> 5;
    const int lane = t & 31;
    const int rin  = lane & 15;
    const int hb   = lane >> 4;
    const int bh   = blockIdx.y;
    const int b    = bh >> 4;
    const int h    = bh & 15;
    const int n0   = blockIdx.x * 128;

    const size_t base = (size_t)b * SEQ * DIMD + (size_t)h * HD;

    // ---- stage Q tile: 128 rows x 64 d fp16 (1 row/thread, all 8 chunks) ----
    {
        const __half* src = Qh + base + (size_t)(n0 + t) * DIMD;
        #pragma unroll
        for (int g = 0; g < 8; g++)
            st16(sw_addr(Qs, t, g), *(const uint4*)(src + g * 8));
    }

    // K/V cp.async staging: per thread 4 K-chunks + 4 V-chunks.
    const int srow = t >> 1;
    const int scol = (t & 1) * 4;
    auto stageKV = [&](int m0, uint32_t bufbase) {
        const __half* kp = Kh + base + (size_t)(m0 + srow) * DIMD + scol * 8;
        const __half* vp = Vh + base + (size_t)(m0 + srow) * DIMD + scol * 8;
        #pragma unroll
        for (int g = 0; g < 4; g++) {
            CP_ASYNC16(sw_addr(bufbase, srow, scol + g),         kp + g * 8);
            CP_ASYNC16(sw_addr(bufbase + 8192u, srow, scol + g), vp + g * 8);
        }
        CP_COMMIT();
    };

    stageKV(0, sb + 16384u);
    __syncthreads();   // Q staging complete

    // ---- load Q fragments once: 2 m-tiles x 4 k-steps ----
    uint32_t qf[2][4][4];
    #pragma unroll
    for (int mi = 0; mi < 2; mi++)
        #pragma unroll
        for (int ks = 0; ks < 4; ks++)
            LDSM_X4(qf[mi][ks][0], qf[mi][ks][1], qf[mi][ks][2], qf[mi][ks][3],
                    sw_addr(Qs, w * 32 + mi * 16 + rin, 2 * ks + hb));

    float oacc[2][8][4];
    #pragma unroll
    for (int mi = 0; mi < 2; mi++)
        #pragma unroll
        for (int j = 0; j < 8; j++)
            #pragma unroll
            for (int q = 0; q < 4; q++) oacc[mi][j][q] = 0.0f;
    float lr[2][2] = {{0.0f, 0.0f}, {0.0f, 0.0f}};

    for (int ch = 0; ch < SEQ / 64; ch++) {
        const uint32_t Ks = sb + 16384u + (uint32_t)(ch & 1) * 16384u;
        const uint32_t Vs = Ks + 8192u;
        CP_WAIT0();
        __syncthreads();
        if (ch + 1 < SEQ / 64)
            stageKV((ch + 1) * 64, sb + 16384u + (uint32_t)((ch + 1) & 1) * 16384u);

        #pragma unroll
        for (int kh = 0; kh < 2; kh++) {
            float sacc[2][4][4];
            #pragma unroll
            for (int mi = 0; mi < 2; mi++)
                #pragma unroll
                for (int j = 0; j < 4; j++)
                    #pragma unroll
                    for (int q = 0; q < 4; q++) sacc[mi][j][q] = 0.0f;

            #pragma unroll
            for (int ks = 0; ks < 4; ks++) {
                uint32_t kb[2][4];
                #pragma unroll
                for (int pi = 0; pi < 2; pi++)
                    LDSM_X4(kb[pi][0], kb[pi][1], kb[pi][2], kb[pi][3],
                            sw_addr(Ks, kh * 32 + pi * 16 + rin, 2 * ks + hb));
                #pragma unroll
                for (int mi = 0; mi < 2; mi++)
                    #pragma unroll
                    for (int pi = 0; pi < 2; pi++) {
                        MMA_F16(sacc[mi][2 * pi],     qf[mi][ks], kb[pi][0], kb[pi][2]);
                        MMA_F16(sacc[mi][2 * pi + 1], qf[mi][ks], kb[pi][1], kb[pi][3]);
                    }
            }

            uint32_t pf[2][4][2];
            #pragma unroll
            for (int mi = 0; mi < 2; mi++)
                #pragma unroll
                for (int j = 0; j < 4; j++) {
                    float p0 = __expf(sacc[mi][j][0] * 0.03125f);
                    float p1 = __expf(sacc[mi][j][1] * 0.03125f);
                    float p2 = __expf(sacc[mi][j][2] * 0.03125f);
                    float p3 = __expf(sacc[mi][j][3] * 0.03125f);
                    lr[mi][0] += p0 + p1;
                    lr[mi][1] += p2 + p3;
                    pf[mi][j][0] = pkhf(p0, p1);
                    pf[mi][j][1] = pkhf(p2, p3);
                }

            #pragma unroll
            for (int ks2 = 0; ks2 < 2; ks2++) {
                uint32_t pa[2][4];
                #pragma unroll
                for (int mi = 0; mi < 2; mi++) {
                    pa[mi][0] = pf[mi][2 * ks2][0];     pa[mi][1] = pf[mi][2 * ks2][1];
                    pa[mi][2] = pf[mi][2 * ks2 + 1][0]; pa[mi][3] = pf[mi][2 * ks2 + 1][1];
                }
                #pragma unroll
                for (int pi = 0; pi < 4; pi++) {
                    uint32_t vb0, vb1, vb2, vb3;
                    LDSM_X4_T(vb0, vb1, vb2, vb3,
                              sw_addr(Vs, kh * 32 + ks2 * 16 + rin, 2 * pi + hb));
                    #pragma unroll
                    for (int mi = 0; mi < 2; mi++) {
                        MMA_F16(oacc[mi][2 * pi],     pa[mi], vb0, vb1);
                        MMA_F16(oacc[mi][2 * pi + 1], pa[mi], vb2, vb3);
                    }
                }
            }
        }
        __syncthreads();   // all reads of this buffer done before its restage
    }

    // ---- finalize: quad-reduce l, O = acc/l + Q (residual from smem Qs) ----
    #pragma unroll
    for (int mi = 0; mi < 2; mi++) {
        lr[mi][0] += __shfl_xor_sync(0xffffffffu, lr[mi][0], 1);
        lr[mi][0] += __shfl_xor_sync(0xffffffffu, lr[mi][0], 2);
        lr[mi][1] += __shfl_xor_sync(0xffffffffu, lr[mi][1], 1);
        lr[mi][1] += __shfl_xor_sync(0xffffffffu, lr[mi][1], 2);
        const float inv0 = 1.0f / lr[mi][0];
        const float inv1 = 1.0f / lr[mi][1];

        const int rl0 = w * 32 + mi * 16 + (lane >> 2);
        const int rl1 = rl0 + 8;
        #pragma unroll
        for (int j = 0; j < 8; j++) {
            const int col = j * 8 + (lane & 3) * 2;
            uint32_t q0u, q1u;
            asm volatile("ld.shared.b32 %0, [%1];" : "=r"(q0u)
                         : "r"(sw_addr(Qs, rl0, col >> 3) + (uint32_t)((col & 7) * 2)));
            asm volatile("ld.shared.b32 %0, [%1];" : "=r"(q1u)
                         : "r"(sw_addr(Qs, rl1, col >> 3) + (uint32_t)((col & 7) * 2)));
            float2 q0 = __half22float2(*(__half2*)&q0u);
            float2 q1 = __half22float2(*(__half2*)&q1u);
            float o00 = oacc[mi][j][0] * inv0 + q0.x;
            float o01 = oacc[mi][j][1] * inv0 + q0.y;
            float o10 = oacc[mi][j][2] * inv1 + q1.x;
            float o11 = oacc[mi][j][3] * inv1 + q1.y;
            *(uint32_t*)&OhH[base + (size_t)(n0 + rl0) * DIMD + col] = pkhf(o00, o01);
            *(uint32_t*)&OhH[base + (size_t)(n0 + rl1) * DIMD + col] = pkhf(o10, o11);
        }
    }
}

// ================================================================================
extern "C" void kernel_launch(void* const* d_in, const int* in_sizes, int n_in,
                              void* d_out, int out_size)
{
    const float* Q  = (const float*)d_in[0];
    const float* K  = (const float*)d_in[1];
    const float* Wq = (const float*)d_in[2];
    const float* bq = (const float*)d_in[3];
    const float* Wk = (const float*)d_in[4];
    const float* bk = (const float*)d_in[5];
    const float* Wv = (const float*)d_in[6];
    const float* bv = (const float*)d_in[7];
    const float* Wo = (const float*)d_in[8];
    const float* bo = (const float*)d_in[9];
    float* out = (float*)d_out;

    __half *Qh, *Kh, *Vh, *OhH, *XqH, *XkH, *WqH, *WkH, *WvH, *WoH;
    cudaGetSymbolAddress((void**)&Qh,  g_Qh);
    cudaGetSymbolAddress((void**)&Kh,  g_Kh);
    cudaGetSymbolAddress((void**)&Vh,  g_Vh);
    cudaGetSymbolAddress((void**)&OhH, g_OhH);
    cudaGetSymbolAddress((void**)&XqH, g_XqH);
    cudaGetSymbolAddress((void**)&XkH, g_XkH);
    cudaGetSymbolAddress((void**)&WqH, g_WqH);
    cudaGetSymbolAddress((void**)&WkH, g_WkH);
    cudaGetSymbolAddress((void**)&WvH, g_WvH);
    cudaGetSymbolAddress((void**)&WoH, g_WoH);

    cudaFuncSetAttribute(attn_mma,
                         cudaFuncAttributeMaxDynamicSharedMemorySize, ATT_SMEM);
    cudaFuncSetAttribute(gemm16<0>,
                         cudaFuncAttributeMaxDynamicSharedMemorySize, GEMM_SMEM);
    cudaFuncSetAttribute(gemm16<2>,
                         cudaFuncAttributeMaxDynamicSharedMemorySize, GEMM_SMEM);

    const int nX = TT * DIMD, nW = DIMD * DIMD;
    f2h_kernel<<<nX / 2048, 256>>>(Q,  XqH, nX);
    f2h_kernel<<<nX / 2048, 256>>>(K,  XkH, nX);
    f2h_kernel<<<nW / 2048, 256>>>(Wq, WqH, nW);
    f2h_kernel<<<nW / 2048, 256>>>(Wk, WkH, nW);
    f2h_kernel<<<nW / 2048, 256>>>(Wv, WvH, nW);
    f2h_kernel<<<nW / 2048, 256>>>(Wo, WoH, nW);

    dim3 gg(DIMD / 256, TT / 128);   // (4, 64)
    gemm16<0><<<gg, 256, GEMM_SMEM>>>(XqH, WqH, bq, nullptr, nullptr, Qh);
    gemm16<0><<<gg, 256, GEMM_SMEM>>>(XkH, WkH, bk, nullptr, nullptr, Kh);
    gemm16<0><<<gg, 256, GEMM_SMEM>>>(XkH, WvH, bv, nullptr, nullptr, Vh);
    attn_mma<<<dim3(16, 64), 128, ATT_SMEM>>>(Qh, Kh, Vh, OhH);
    gemm16<2><<<gg, 256, GEMM_SMEM>>>(OhH, WoH, bo, OhH, out, nullptr);
}

// round 17
// speedup vs baseline: 1.2875x; 1.0124x over previous
#include <cuda_runtime.h>
#include <cuda_fp16.h>
#include <cstdint>
#include <cstddef>

#define DIMD   1024
#define TT     8192     // B*N = B*M rows
#define HD     64       // head dim
#define SEQ    2048

// ---------------- scratch ----------------
__device__ __half g_Qh [TT * DIMD];
__device__ __half g_Kh [TT * DIMD];
__device__ __half g_Vh [TT * DIMD];
__device__ __half g_OhH[TT * DIMD];
__device__ __half g_XqH[TT * DIMD];
__device__ __half g_XkH[TT * DIMD];
__device__ __half g_WqH[DIMD * DIMD];
__device__ __half g_WkH[DIMD * DIMD];
__device__ __half g_WvH[DIMD * DIMD];
__device__ __half g_WoH[DIMD * DIMD];

// =========================== helpers =================================
__device__ __forceinline__ uint32_t smem_u32(const void* p) {
    uint32_t a;
    asm("{ .reg .u64 t; cvta.to.shared.u64 t, %1; cvt.u32.u64 %0, t; }"
        : "=r"(a) : "l"(p));
    return a;
}

#define LDSM_X4(R0, R1, R2, R3, addr) \
    asm volatile("ldmatrix.sync.aligned.m8n8.x4.shared.b16 {%0,%1,%2,%3}, [%4];" \
                 : "=r"(R0), "=r"(R1), "=r"(R2), "=r"(R3) : "r"(addr))

#define LDSM_X4_T(R0, R1, R2, R3, addr) \
    asm volatile("ldmatrix.sync.aligned.m8n8.x4.trans.shared.b16 {%0,%1,%2,%3}, [%4];" \
                 : "=r"(R0), "=r"(R1), "=r"(R2), "=r"(R3) : "r"(addr))

#define MMA_F16(c, a, b0, b1) \
    asm volatile("mma.sync.aligned.m16n8k16.row.col.f32.f16.f16.f32 " \
                 "{%0,%1,%2,%3}, {%4,%5,%6,%7}, {%8,%9}, {%0,%1,%2,%3};" \
                 : "+f"((c)[0]), "+f"((c)[1]), "+f"((c)[2]), "+f"((c)[3]) \
                 : "r"((a)[0]), "r"((a)[1]), "r"((a)[2]), "r"((a)[3]), \
                   "r"(b0), "r"(b1))

#define CP_ASYNC16(smem, gptr) \
    asm volatile("cp.async.cg.shared.global [%0], [%1], 16;" \
                 :: "r"(smem), "l"(gptr) : "memory")
#define CP_COMMIT() asm volatile("cp.async.commit_group;" ::: "memory")
#define CP_WAIT0()  asm volatile("cp.async.wait_group 0;" ::: "memory")

__device__ __forceinline__ uint32_t pkhf(float lo, float hi) {
    uint32_t d;
    asm("cvt.rn.f16x2.f32 %0, %1, %2;" : "=r"(d) : "f"(hi), "f"(lo));
    return d;
}

// swizzled smem address: 128B rows, 8 chunks of 16B, chunk c XOR (r&7)
__device__ __forceinline__ uint32_t sw_addr(uint32_t base, int r, int c) {
    return base + (uint32_t)(r * 128) + (uint32_t)(((c ^ (r & 7)) & 7) << 4);
}

__device__ __forceinline__ void st16(uint32_t a, uint4 v) {
    asm volatile("st.shared.v4.b32 [%0], {%1,%2,%3,%4};"
                 :: "r"(a), "r"(v.x), "r"(v.y), "r"(v.z), "r"(v.w));
}

// ================================================================================
// fp32 -> fp16 conversion, 16 elems/thread, blockIdx.y selects the array pair.
// ================================================================================
__global__ void __launch_bounds__(256)
f2h2_kernel(const float* __restrict__ inA, __half* __restrict__ outA,
            const float* __restrict__ inB, __half* __restrict__ outB, int n)
{
    const float* in  = blockIdx.y ? inB  : inA;
    __half*      out = blockIdx.y ? outB : outA;
    int i = (blockIdx.x * 256 + threadIdx.x) * 16;
    if (i >= n) return;
    float4 a = *(const float4*)(in + i);
    float4 b = *(const float4*)(in + i + 4);
    float4 c = *(const float4*)(in + i + 8);
    float4 d = *(const float4*)(in + i + 12);
    uint4 o0, o1;
    o0.x = pkhf(a.x, a.y); o0.y = pkhf(a.z, a.w);
    o0.z = pkhf(b.x, b.y); o0.w = pkhf(b.z, b.w);
    o1.x = pkhf(c.x, c.y); o1.y = pkhf(c.z, c.w);
    o1.z = pkhf(d.x, d.y); o1.w = pkhf(d.z, d.w);
    *(uint4*)(out + i)     = o0;
    *(uint4*)(out + i + 8) = o1;
}

__global__ void __launch_bounds__(256)
f2h4_kernel(const float* __restrict__ i0, __half* __restrict__ o0p,
            const float* __restrict__ i1, __half* __restrict__ o1p,
            const float* __restrict__ i2, __half* __restrict__ o2p,
            const float* __restrict__ i3, __half* __restrict__ o3p, int n)
{
    int y = blockIdx.y;
    const float* in  = (y == 0) ? i0 : (y == 1) ? i1 : (y == 2) ? i2 : i3;
    __half*      out = (y == 0) ? o0p : (y == 1) ? o1p : (y == 2) ? o2p : o3p;
    int i = (blockIdx.x * 256 + threadIdx.x) * 16;
    if (i >= n) return;
    float4 a = *(const float4*)(in + i);
    float4 b = *(const float4*)(in + i + 4);
    float4 c = *(const float4*)(in + i + 8);
    float4 d = *(const float4*)(in + i + 12);
    uint4 o0, o1;
    o0.x = pkhf(a.x, a.y); o0.y = pkhf(a.z, a.w);
    o0.z = pkhf(b.x, b.y); o0.w = pkhf(b.z, b.w);
    o1.x = pkhf(c.x, c.y); o1.y = pkhf(c.z, c.w);
    o1.z = pkhf(d.x, d.y); o1.w = pkhf(d.z, d.w);
    *(uint4*)(out + i)     = o0;
    *(uint4*)(out + i + 8) = o1;
}

// ================================================================================
// All-fp16 GEMM core, cp.async staging, CTA tile 128x256, warp tile 64x64, BK=64.
// ================================================================================
#define GEMM_SMEM (2 * 49152)

template <int MODE>   // 0: fp16 CH   2: fp32 C32 = Rh + relu(acc+bias)
__device__ __forceinline__ void gemm16_body(
    const __half* __restrict__ X, const __half* __restrict__ W,
    const float* __restrict__ bias, const __half* __restrict__ Rh,
    float* __restrict__ C32, __half* __restrict__ CH,
    int bn, int bm, uint32_t sb)
{
    const int t    = threadIdx.x;
    const int w    = t >> 5;
    const int lane = t & 31;
    const int wm   = w >> 2;
    const int wn   = w & 3;
    const int rin  = lane & 15;
    const int hb   = lane >> 4;

    float acc[4][8][4];
    #pragma unroll
    for (int mi = 0; mi < 4; mi++)
        #pragma unroll
        for (int ni = 0; ni < 8; ni++)
            #pragma unroll
            for (int q = 0; q < 4; q++) acc[mi][ni][q] = 0.0f;

    auto stage = [&](int ch, uint32_t buf) {
        const int k0 = ch * 64;
        #pragma unroll
        for (int s = 0; s < 4; s++) {
            int idx = t + 256 * s;
            int r = idx >> 3, c = idx & 7;
            CP_ASYNC16(sw_addr(buf, r, c),
                       X + (size_t)(bm * 128 + r) * DIMD + k0 + c * 8);
        }
        #pragma unroll
        for (int s = 0; s < 8; s++) {
            int idx = t + 256 * s;
            int r = idx >> 3, c = idx & 7;
            CP_ASYNC16(sw_addr(buf + 16384u, r, c),
                       W + (size_t)(bn * 256 + r) * DIMD + k0 + c * 8);
        }
        CP_COMMIT();
    };

    stage(0, sb);

    for (int ch = 0; ch < 16; ch++) {
        const uint32_t buf = sb + (uint32_t)(ch & 1) * 49152u;
        CP_WAIT0();
        __syncthreads();
        if (ch + 1 < 16)
            stage(ch + 1, sb + (uint32_t)((ch + 1) & 1) * 49152u);

        #pragma unroll
        for (int ks = 0; ks < 4; ks++) {
            const int chi = 2 * ks + hb;
            uint32_t afr[4][4];
            #pragma unroll
            for (int mi = 0; mi < 4; mi++)
                LDSM_X4(afr[mi][0], afr[mi][1], afr[mi][2], afr[mi][3],
                        sw_addr(buf, wm * 64 + mi * 16 + rin, chi));
            uint32_t bf[4][4];
            #pragma unroll
            for (int pi = 0; pi < 4; pi++)
                LDSM_X4(bf[pi][0], bf[pi][1], bf[pi][2], bf[pi][3],
                        sw_addr(buf + 16384u, wn * 64 + pi * 16 + rin, chi));
            #pragma unroll
            for (int mi = 0; mi < 4; mi++)
                #pragma unroll
                for (int pi = 0; pi < 4; pi++) {
                    MMA_F16(acc[mi][2 * pi],     afr[mi], bf[pi][0], bf[pi][2]);
                    MMA_F16(acc[mi][2 * pi + 1], afr[mi], bf[pi][1], bf[pi][3]);
                }
        }
    }

    // ------------------------- epilogue -------------------------
    const int rbase = bm * 128 + wm * 64;
    const int cbase = bn * 256 + wn * 64;
    float bb[8][2];
    #pragma unroll
    for (int ni = 0; ni < 8; ni++) {
        int c0 = cbase + ni * 8 + (lane & 3) * 2;
        bb[ni][0] = bias[c0];
        bb[ni][1] = bias[c0 + 1];
    }

    #pragma unroll
    for (int mi = 0; mi < 4; mi++) {
        #pragma unroll
        for (int ni = 0; ni < 8; ni++) {
            int r0 = rbase + mi * 16 + (lane >> 2);
            int c0 = cbase + ni * 8 + (lane & 3) * 2;
            float o0 = acc[mi][ni][0] + bb[ni][0];
            float o1 = acc[mi][ni][1] + bb[ni][1];
            float o2 = acc[mi][ni][2] + bb[ni][0];
            float o3 = acc[mi][ni][3] + bb[ni][1];
            if (MODE == 2) {
                __half2 ra = *(const __half2*)&Rh[(size_t)r0 * DIMD + c0];
                __half2 rb = *(const __half2*)&Rh[(size_t)(r0 + 8) * DIMD + c0];
                float2 raf = __half22float2(ra);
                float2 rbf = __half22float2(rb);
                o0 = fmaxf(o0, 0.0f) + raf.x;
                o1 = fmaxf(o1, 0.0f) + raf.y;
                o2 = fmaxf(o2, 0.0f) + rbf.x;
                o3 = fmaxf(o3, 0.0f) + rbf.y;
                *(float2*)&C32[(size_t)r0 * DIMD + c0]       = make_float2(o0, o1);
                *(float2*)&C32[(size_t)(r0 + 8) * DIMD + c0] = make_float2(o2, o3);
            } else {
                *(uint32_t*)&CH[(size_t)r0 * DIMD + c0]       = pkhf(o0, o1);
                *(uint32_t*)&CH[(size_t)(r0 + 8) * DIMD + c0] = pkhf(o2, o3);
            }
        }
    }
}

// fused Q/K/V projection: blockIdx.z selects (X, W, bias, CH)
__global__ void __launch_bounds__(256)
gemm_proj3(const __half* __restrict__ XqH, const __half* __restrict__ XkH,
           const __half* __restrict__ WqH, const __half* __restrict__ WkH,
           const __half* __restrict__ WvH,
           const float* __restrict__ bq, const float* __restrict__ bk,
           const float* __restrict__ bv,
           __half* __restrict__ Qh, __half* __restrict__ Kh,
           __half* __restrict__ Vh)
{
    extern __shared__ char sm[];
    const int z = blockIdx.z;
    const __half* X    = (z == 0) ? XqH : XkH;
    const __half* W    = (z == 0) ? WqH : (z == 1) ? WkH : WvH;
    const float*  bias = (z == 0) ? bq  : (z == 1) ? bk  : bv;
    __half*       CH   = (z == 0) ? Qh  : (z == 1) ? Kh  : Vh;
    gemm16_body<0>(X, W, bias, nullptr, nullptr, CH,
                   blockIdx.x, blockIdx.y, smem_u32(sm));
}

// output GEMM: fp32 out = OhH + relu(OhH @ Wo^T + bo)
__global__ void __launch_bounds__(256)
gemm_out(const __half* __restrict__ X, const __half* __restrict__ W,
         const float* __restrict__ bias, const __half* __restrict__ Rh,
         float* __restrict__ C32)
{
    extern __shared__ char sm[];
    gemm16_body<2>(X, W, bias, Rh, C32, nullptr,
                   blockIdx.x, blockIdx.y, smem_u32(sm));
}

// ================================================================================
// Tensor-core flash attention (R16-proven, unchanged): Br=128, Bc=64, d=64,
// 4 warps, 32 Q-rows/warp, cp.async K/V double-buffer, smem Q-residual,
// fp16 OhH output only.
// ================================================================================
#define ATT_SMEM (16384 + 2 * 16384)

__global__ void __launch_bounds__(128, 2)
attn_mma(const __half* __restrict__ Qh, const __half* __restrict__ Kh,
         const __half* __restrict__ Vh, __half* __restrict__ OhH)
{
    extern __shared__ char smatt[];
    const uint32_t sb = smem_u32(smatt);
    const uint32_t Qs = sb;

    const int t    = threadIdx.x;
    const int w    = t >> 5;
    const int lane = t & 31;
    const int rin  = lane & 15;
    const int hb   = lane >> 4;
    const int bh   = blockIdx.y;
    const int b    = bh >> 4;
    const int h    = bh & 15;
    const int n0   = blockIdx.x * 128;

    const size_t base = (size_t)b * SEQ * DIMD + (size_t)h * HD;

    {
        const __half* src = Qh + base + (size_t)(n0 + t) * DIMD;
        #pragma unroll
        for (int g = 0; g < 8; g++)
            st16(sw_addr(Qs, t, g), *(const uint4*)(src + g * 8));
    }

    const int srow = t >> 1;
    const int scol = (t & 1) * 4;
    auto stageKV = [&](int m0, uint32_t bufbase) {
        const __half* kp = Kh + base + (size_t)(m0 + srow) * DIMD + scol * 8;
        const __half* vp = Vh + base + (size_t)(m0 + srow) * DIMD + scol * 8;
        #pragma unroll
        for (int g = 0; g < 4; g++) {
            CP_ASYNC16(sw_addr(bufbase, srow, scol + g),         kp + g * 8);
            CP_ASYNC16(sw_addr(bufbase + 8192u, srow, scol + g), vp + g * 8);
        }
        CP_COMMIT();
    };

    stageKV(0, sb + 16384u);
    __syncthreads();

    uint32_t qf[2][4][4];
    #pragma unroll
    for (int mi = 0; mi < 2; mi++)
        #pragma unroll
        for (int ks = 0; ks < 4; ks++)
            LDSM_X4(qf[mi][ks][0], qf[mi][ks][1], qf[mi][ks][2], qf[mi][ks][3],
                    sw_addr(Qs, w * 32 + mi * 16 + rin, 2 * ks + hb));

    float oacc[2][8][4];
    #pragma unroll
    for (int mi = 0; mi < 2; mi++)
        #pragma unroll
        for (int j = 0; j < 8; j++)
            #pragma unroll
            for (int q = 0; q < 4; q++) oacc[mi][j][q] = 0.0f;
    float lr[2][2] = {{0.0f, 0.0f}, {0.0f, 0.0f}};

    for (int ch = 0; ch < SEQ / 64; ch++) {
        const uint32_t Ks = sb + 16384u + (uint32_t)(ch & 1) * 16384u;
        const uint32_t Vs = Ks + 8192u;
        CP_WAIT0();
        __syncthreads();
        if (ch + 1 < SEQ / 64)
            stageKV((ch + 1) * 64, sb + 16384u + (uint32_t)((ch + 1) & 1) * 16384u);

        #pragma unroll
        for (int kh = 0; kh < 2; kh++) {
            float sacc[2][4][4];
            #pragma unroll
            for (int mi = 0; mi < 2; mi++)
                #pragma unroll
                for (int j = 0; j < 4; j++)
                    #pragma unroll
                    for (int q = 0; q < 4; q++) sacc[mi][j][q] = 0.0f;

            #pragma unroll
            for (int ks = 0; ks < 4; ks++) {
                uint32_t kb[2][4];
                #pragma unroll
                for (int pi = 0; pi < 2; pi++)
                    LDSM_X4(kb[pi][0], kb[pi][1], kb[pi][2], kb[pi][3],
                            sw_addr(Ks, kh * 32 + pi * 16 + rin, 2 * ks + hb));
                #pragma unroll
                for (int mi = 0; mi < 2; mi++)
                    #pragma unroll
                    for (int pi = 0; pi < 2; pi++) {
                        MMA_F16(sacc[mi][2 * pi],     qf[mi][ks], kb[pi][0], kb[pi][2]);
                        MMA_F16(sacc[mi][2 * pi + 1], qf[mi][ks], kb[pi][1], kb[pi][3]);
                    }
            }

            uint32_t pf[2][4][2];
            #pragma unroll
            for (int mi = 0; mi < 2; mi++)
                #pragma unroll
                for (int j = 0; j < 4; j++) {
                    float p0 = __expf(sacc[mi][j][0] * 0.03125f);
                    float p1 = __expf(sacc[mi][j][1] * 0.03125f);
                    float p2 = __expf(sacc[mi][j][2] * 0.03125f);
                    float p3 = __expf(sacc[mi][j][3] * 0.03125f);
                    lr[mi][0] += p0 + p1;
                    lr[mi][1] += p2 + p3;
                    pf[mi][j][0] = pkhf(p0, p1);
                    pf[mi][j][1] = pkhf(p2, p3);
                }

            #pragma unroll
            for (int ks2 = 0; ks2 < 2; ks2++) {
                uint32_t pa[2][4];
                #pragma unroll
                for (int mi = 0; mi < 2; mi++) {
                    pa[mi][0] = pf[mi][2 * ks2][0];     pa[mi][1] = pf[mi][2 * ks2][1];
                    pa[mi][2] = pf[mi][2 * ks2 + 1][0]; pa[mi][3] = pf[mi][2 * ks2 + 1][1];
                }
                #pragma unroll
                for (int pi = 0; pi < 4; pi++) {
                    uint32_t vb0, vb1, vb2, vb3;
                    LDSM_X4_T(vb0, vb1, vb2, vb3,
                              sw_addr(Vs, kh * 32 + ks2 * 16 + rin, 2 * pi + hb));
                    #pragma unroll
                    for (int mi = 0; mi < 2; mi++) {
                        MMA_F16(oacc[mi][2 * pi],     pa[mi], vb0, vb1);
                        MMA_F16(oacc[mi][2 * pi + 1], pa[mi], vb2, vb3);
                    }
                }
            }
        }
        __syncthreads();
    }

    #pragma unroll
    for (int mi = 0; mi < 2; mi++) {
        lr[mi][0] += __shfl_xor_sync(0xffffffffu, lr[mi][0], 1);
        lr[mi][0] += __shfl_xor_sync(0xffffffffu, lr[mi][0], 2);
        lr[mi][1] += __shfl_xor_sync(0xffffffffu, lr[mi][1], 1);
        lr[mi][1] += __shfl_xor_sync(0xffffffffu, lr[mi][1], 2);
        const float inv0 = 1.0f / lr[mi][0];
        const float inv1 = 1.0f / lr[mi][1];

        const int rl0 = w * 32 + mi * 16 + (lane >> 2);
        const int rl1 = rl0 + 8;
        #pragma unroll
        for (int j = 0; j < 8; j++) {
            const int col = j * 8 + (lane & 3) * 2;
            uint32_t q0u, q1u;
            asm volatile("ld.shared.b32 %0, [%1];" : "=r"(q0u)
                         : "r"(sw_addr(Qs, rl0, col >> 3) + (uint32_t)((col & 7) * 2)));
            asm volatile("ld.shared.b32 %0, [%1];" : "=r"(q1u)
                         : "r"(sw_addr(Qs, rl1, col >> 3) + (uint32_t)((col & 7) * 2)));
            float2 q0 = __half22float2(*(__half2*)&q0u);
            float2 q1 = __half22float2(*(__half2*)&q1u);
            float o00 = oacc[mi][j][0] * inv0 + q0.x;
            float o01 = oacc[mi][j][1] * inv0 + q0.y;
            float o10 = oacc[mi][j][2] * inv1 + q1.x;
            float o11 = oacc[mi][j][3] * inv1 + q1.y;
            *(uint32_t*)&OhH[base + (size_t)(n0 + rl0) * DIMD + col] = pkhf(o00, o01);
            *(uint32_t*)&OhH[base + (size_t)(n0 + rl1) * DIMD + col] = pkhf(o10, o11);
        }
    }
}

// ================================================================================
extern "C" void kernel_launch(void* const* d_in, const int* in_sizes, int n_in,
                              void* d_out, int out_size)
{
    const float* Q  = (const float*)d_in[0];
    const float* K  = (const float*)d_in[1];
    const float* Wq = (const float*)d_in[2];
    const float* bq = (const float*)d_in[3];
    const float* Wk = (const float*)d_in[4];
    const float* bk = (const float*)d_in[5];
    const float* Wv = (const float*)d_in[6];
    const float* bv = (const float*)d_in[7];
    const float* Wo = (const float*)d_in[8];
    const float* bo = (const float*)d_in[9];
    float* out = (float*)d_out;

    __half *Qh, *Kh, *Vh, *OhH, *XqH, *XkH, *WqH, *WkH, *WvH, *WoH;
    cudaGetSymbolAddress((void**)&Qh,  g_Qh);
    cudaGetSymbolAddress((void**)&Kh,  g_Kh);
    cudaGetSymbolAddress((void**)&Vh,  g_Vh);
    cudaGetSymbolAddress((void**)&OhH, g_OhH);
    cudaGetSymbolAddress((void**)&XqH, g_XqH);
    cudaGetSymbolAddress((void**)&XkH, g_XkH);
    cudaGetSymbolAddress((void**)&WqH, g_WqH);
    cudaGetSymbolAddress((void**)&WkH, g_WkH);
    cudaGetSymbolAddress((void**)&WvH, g_WvH);
    cudaGetSymbolAddress((void**)&WoH, g_WoH);

    cudaFuncSetAttribute(attn_mma,
                         cudaFuncAttributeMaxDynamicSharedMemorySize, ATT_SMEM);
    cudaFuncSetAttribute(gemm_proj3,
                         cudaFuncAttributeMaxDynamicSharedMemorySize, GEMM_SMEM);
    cudaFuncSetAttribute(gemm_out,
                         cudaFuncAttributeMaxDynamicSharedMemorySize, GEMM_SMEM);

    const int nX = TT * DIMD, nW = DIMD * DIMD;
    f2h2_kernel<<<dim3(nX / 4096, 2), 256>>>(Q, XqH, K, XkH, nX);
    f2h4_kernel<<<dim3(nW / 4096, 4), 256>>>(Wq, WqH, Wk, WkH, Wv, WvH, Wo, WoH, nW);

    gemm_proj3<<<dim3(DIMD / 256, TT / 128, 3), 256, GEMM_SMEM>>>(
        XqH, XkH, WqH, WkH, WvH, bq, bk, bv, Qh, Kh, Vh);
    attn_mma<<<dim3(16, 64), 128, ATT_SMEM>>>(Qh, Kh, Vh, OhH);
    gemm_out<<<dim3(DIMD / 256, TT / 128), 256, GEMM_SMEM>>>(OhH, WoH, bo, OhH, out);
}